// round 1
// baseline (speedup 1.0000x reference)
#include <cuda_runtime.h>
#include <cuda_bf16.h>

// SeparationLoss: mean over B of sum_{i!=j} max(0, thr2 - ||kp_i - kp_j||^2)
// Input: batched_kps [B, 17, 3] f32 (B = 131072 in the bench).
// Output: scalar f32.

#define J 17
#define DIMS 3
#define ROW_F (J * DIMS)          // 51 floats per row
#define ROWS_PER_BLOCK 256
#define THREADS 256
#define MAX_BLOCKS 2048

__device__ float g_partials[MAX_BLOCKS];

__global__ __launch_bounds__(THREADS)
void sep_loss_main(const float* __restrict__ kps, int B) {
    __shared__ float s[ROWS_PER_BLOCK * ROW_F];   // 52224 bytes

    const int tid = threadIdx.x;
    const int rowBase = blockIdx.x * ROWS_PER_BLOCK;
    const int rowsHere = min(ROWS_PER_BLOCK, B - rowBase);

    // ---- coalesced staged load: tile is 256*51 floats = 3264 float4, 16B aligned ----
    if (rowsHere == ROWS_PER_BLOCK) {
        const float4* __restrict__ src =
            reinterpret_cast<const float4*>(kps + (size_t)rowBase * ROW_F);
        float4* dst = reinterpret_cast<float4*>(s);
        const int nvec = ROWS_PER_BLOCK * ROW_F / 4;  // 3264
        #pragma unroll
        for (int i = tid; i < nvec; i += THREADS) dst[i] = src[i];
    } else {
        // tail block (not hit for B=131072, kept for generality)
        const int nflt = rowsHere * ROW_F;
        const float* src = kps + (size_t)rowBase * ROW_F;
        for (int i = tid; i < nflt; i += THREADS) s[i] = src[i];
    }
    __syncthreads();

    float acc = 0.0f;
    if (tid < rowsHere) {
        // SMEM -> registers, stride 51 words: conflict-free (gcd(51,32)=1)
        float p[ROW_F];
        #pragma unroll
        for (int i = 0; i < ROW_F; i++) p[i] = s[tid * ROW_F + i];

        const float thr2 = 0.01f;  // THRESHOLD^2
        #pragma unroll
        for (int i = 0; i < J; i++) {
            #pragma unroll
            for (int j = i + 1; j < J; j++) {
                float dx = p[3 * i + 0] - p[3 * j + 0];
                float dy = p[3 * i + 1] - p[3 * j + 1];
                float dz = p[3 * i + 2] - p[3 * j + 2];
                // t = d2 - thr2 ; hinge = max(0, -t)
                float t = fmaf(dx, dx, fmaf(dy, dy, fmaf(dz, dz, -thr2)));
                acc += fmaxf(0.0f, -t);
            }
        }
        acc *= 2.0f;  // ordered pairs
    }

    // ---- deterministic block reduction ----
    // warp-level
    #pragma unroll
    for (int off = 16; off > 0; off >>= 1)
        acc += __shfl_down_sync(0xFFFFFFFFu, acc, off);

    __shared__ float wsum[THREADS / 32];
    if ((tid & 31) == 0) wsum[tid >> 5] = acc;
    __syncthreads();
    if (tid < THREADS / 32) {
        float v = wsum[tid];
        #pragma unroll
        for (int off = (THREADS / 64); off > 0; off >>= 1)
            v += __shfl_down_sync(0xFFu, v, off);
        if (tid == 0) g_partials[blockIdx.x] = v;
    }
}

__global__ __launch_bounds__(256)
void sep_loss_reduce(float* __restrict__ out, int nblocks, float invB) {
    __shared__ float sh[256];
    float v = 0.0f;
    for (int i = threadIdx.x; i < nblocks; i += 256) v += g_partials[i];
    sh[threadIdx.x] = v;
    __syncthreads();
    #pragma unroll
    for (int s = 128; s > 0; s >>= 1) {
        if (threadIdx.x < s) sh[threadIdx.x] += sh[threadIdx.x + s];
        __syncthreads();
    }
    if (threadIdx.x == 0) out[0] = sh[0] * invB;
}

extern "C" void kernel_launch(void* const* d_in, const int* in_sizes, int n_in,
                              void* d_out, int out_size) {
    const float* kps = (const float*)d_in[0];
    const int B = in_sizes[0] / ROW_F;
    const int nblocks = (B + ROWS_PER_BLOCK - 1) / ROWS_PER_BLOCK;  // 512 for B=131072

    sep_loss_main<<<nblocks, THREADS>>>(kps, B);
    sep_loss_reduce<<<1, 256>>>((float*)d_out, nblocks, 1.0f / (float)B);
}